// round 8
// baseline (speedup 1.0000x reference)
#include <cuda_runtime.h>
#include <cuda_bf16.h>

// Inputs (metadata order):
//   d_in[0] input_values   float32 [1024]
//   d_in[1] weight_matrix  float32 [16384*16384] row-major
//   d_in[2] biases         float32 [16384]
//   d_in[3] act_ids        int32   [16384]   0=identity 1=relu 2=softsign
//   d_in[4] input_indices  int32   [1024]
//   d_in[5] output_indices int32   [256]
// Output: float32 [256]
//
// out[o] = act( sum_i in_vals[i] * W[in_idx[i], out_idx[o]] + bias[out_idx[o]] )
//
// Single launch, one CTA (256 thr) per output. Fast path (n_in multiple of
// 1024-wide vector tiles): each thread does ONE int4 + ONE float4 metadata
// load, then 4 independent scattered W loads with 32-bit address math
// (row*16384 + j < 2^28, fits int). Short 8-warp reduction, inline finalize.

#define BLOCK 256

__global__ void __launch_bounds__(BLOCK, 4)
custom_network_kernel(const float* __restrict__ in_vals,
                      const float* __restrict__ W,
                      const float* __restrict__ bias,
                      const int*   __restrict__ act_ids,
                      const int*   __restrict__ in_idx,
                      const int*   __restrict__ out_idx,
                      float*       __restrict__ out,
                      int n_in, int N)
{
    const int t = threadIdx.x;
    // Issue the uniform out_idx load and the per-thread metadata loads
    // back-to-back so their latencies overlap.
    const int j = __ldg(&out_idx[blockIdx.x]);

    float p = 0.0f;

    if ((n_in & (4 * BLOCK - 1)) == 0) {
        // fast path: vectorized metadata, 4 W-gathers per tile
        const int4*   idx4 = (const int4*)in_idx;
        const float4* val4 = (const float4*)in_vals;
        const int tiles = n_in >> 10;          // n_in / (4*BLOCK)
        for (int ti = 0; ti < tiles; ti++) {
            const int base = ti * BLOCK + t;
            const int4   r4 = __ldg(&idx4[base]);
            const float4 v4 = __ldg(&val4[base]);
            // 4 independent scattered loads, 32-bit addressing
            const float w0 = __ldg(&W[r4.x * N + j]);
            const float w1 = __ldg(&W[r4.y * N + j]);
            const float w2 = __ldg(&W[r4.z * N + j]);
            const float w3 = __ldg(&W[r4.w * N + j]);
            p += v4.x * w0 + v4.y * w1 + v4.z * w2 + v4.w * w3;
        }
    } else {
        for (int i = t; i < n_in; i += BLOCK) {
            const int r = __ldg(&in_idx[i]);
            p += __ldg(&in_vals[i]) * __ldg(&W[r * N + j]);
        }
    }

    // warp reduce (8 warps) then cross-warp combine
    #pragma unroll
    for (int off = 16; off > 0; off >>= 1)
        p += __shfl_xor_sync(0xFFFFFFFFu, p, off);

    __shared__ float sm[BLOCK / 32];
    const int lane = t & 31;
    const int wid  = t >> 5;
    if (lane == 0) sm[wid] = p;
    __syncthreads();

    if (wid == 0) {
        float v = (lane < BLOCK / 32) ? sm[lane] : 0.0f;
        #pragma unroll
        for (int off = 4; off > 0; off >>= 1)
            v += __shfl_xor_sync(0xFFFFFFFFu, v, off);

        if (lane == 0) {
            const float total = v + __ldg(&bias[j]);
            const int   a     = __ldg(&act_ids[j]);
            const float relu  = fmaxf(total, 0.0f);
            const float ssign = total / (1.0f + fabsf(total));
            out[blockIdx.x] = (a == 1) ? relu : ((a == 2) ? ssign : total);
        }
    }
}

extern "C" void kernel_launch(void* const* d_in, const int* in_sizes, int n_in_args,
                              void* d_out, int out_size)
{
    const float* in_vals = (const float*)d_in[0];
    const float* W       = (const float*)d_in[1];
    const float* bias    = (const float*)d_in[2];
    const int*   act_ids = (const int*)  d_in[3];
    const int*   in_idx  = (const int*)  d_in[4];
    const int*   out_idx = (const int*)  d_in[5];
    float*       out     = (float*)      d_out;

    const int n_in = in_sizes[0];   // 1024
    const int N    = in_sizes[2];   // 16384 (bias length)

    custom_network_kernel<<<out_size, BLOCK>>>(
        in_vals, W, bias, act_ids, in_idx, out_idx, out, n_in, N);
}

// round 9
// speedup vs baseline: 1.0047x; 1.0047x over previous
#include <cuda_runtime.h>
#include <cuda_bf16.h>

// Inputs (metadata order):
//   d_in[0] input_values   float32 [1024]
//   d_in[1] weight_matrix  float32 [16384*16384] row-major
//   d_in[2] biases         float32 [16384]
//   d_in[3] act_ids        int32   [16384]   0=identity 1=relu 2=softsign
//   d_in[4] input_indices  int32   [1024]
//   d_in[5] output_indices int32   [256]
// Output: float32 [256]
//
// out[o] = act( sum_i in_vals[i] * W[in_idx[i], out_idx[o]] + bias[out_idx[o]] )
//
// Single launch, one CTA (256 thr) per output. Fast path (n_in multiple of
// 1024-wide vector tiles): each thread does ONE int4 + ONE float4 metadata
// load, then 4 independent scattered W loads with 32-bit address math
// (row*16384 + j < 2^28, fits int). Short 8-warp reduction, inline finalize.

#define BLOCK 256

__global__ void __launch_bounds__(BLOCK, 4)
custom_network_kernel(const float* __restrict__ in_vals,
                      const float* __restrict__ W,
                      const float* __restrict__ bias,
                      const int*   __restrict__ act_ids,
                      const int*   __restrict__ in_idx,
                      const int*   __restrict__ out_idx,
                      float*       __restrict__ out,
                      int n_in, int N)
{
    const int t = threadIdx.x;
    // Issue the uniform out_idx load and the per-thread metadata loads
    // back-to-back so their latencies overlap.
    const int j = __ldg(&out_idx[blockIdx.x]);

    float p = 0.0f;

    if ((n_in & (4 * BLOCK - 1)) == 0) {
        // fast path: vectorized metadata, 4 W-gathers per tile
        const int4*   idx4 = (const int4*)in_idx;
        const float4* val4 = (const float4*)in_vals;
        const int tiles = n_in >> 10;          // n_in / (4*BLOCK)
        for (int ti = 0; ti < tiles; ti++) {
            const int base = ti * BLOCK + t;
            const int4   r4 = __ldg(&idx4[base]);
            const float4 v4 = __ldg(&val4[base]);
            // 4 independent scattered loads, 32-bit addressing
            const float w0 = __ldg(&W[r4.x * N + j]);
            const float w1 = __ldg(&W[r4.y * N + j]);
            const float w2 = __ldg(&W[r4.z * N + j]);
            const float w3 = __ldg(&W[r4.w * N + j]);
            p += v4.x * w0 + v4.y * w1 + v4.z * w2 + v4.w * w3;
        }
    } else {
        for (int i = t; i < n_in; i += BLOCK) {
            const int r = __ldg(&in_idx[i]);
            p += __ldg(&in_vals[i]) * __ldg(&W[r * N + j]);
        }
    }

    // warp reduce (8 warps) then cross-warp combine
    #pragma unroll
    for (int off = 16; off > 0; off >>= 1)
        p += __shfl_xor_sync(0xFFFFFFFFu, p, off);

    __shared__ float sm[BLOCK / 32];
    const int lane = t & 31;
    const int wid  = t >> 5;
    if (lane == 0) sm[wid] = p;
    __syncthreads();

    if (wid == 0) {
        float v = (lane < BLOCK / 32) ? sm[lane] : 0.0f;
        #pragma unroll
        for (int off = 4; off > 0; off >>= 1)
            v += __shfl_xor_sync(0xFFFFFFFFu, v, off);

        if (lane == 0) {
            const float total = v + __ldg(&bias[j]);
            const int   a     = __ldg(&act_ids[j]);
            const float relu  = fmaxf(total, 0.0f);
            const float ssign = total / (1.0f + fabsf(total));
            out[blockIdx.x] = (a == 1) ? relu : ((a == 2) ? ssign : total);
        }
    }
}

extern "C" void kernel_launch(void* const* d_in, const int* in_sizes, int n_in_args,
                              void* d_out, int out_size)
{
    const float* in_vals = (const float*)d_in[0];
    const float* W       = (const float*)d_in[1];
    const float* bias    = (const float*)d_in[2];
    const int*   act_ids = (const int*)  d_in[3];
    const int*   in_idx  = (const int*)  d_in[4];
    const int*   out_idx = (const int*)  d_in[5];
    float*       out     = (float*)      d_out;

    const int n_in = in_sizes[0];   // 1024
    const int N    = in_sizes[2];   // 16384 (bias length)

    custom_network_kernel<<<out_size, BLOCK>>>(
        in_vals, W, bias, act_ids, in_idx, out_idx, out, n_in, N);
}

// round 10
// speedup vs baseline: 1.0385x; 1.0337x over previous
#include <cuda_runtime.h>
#include <cuda_bf16.h>

// Inputs (metadata order):
//   d_in[0] input_values   float32 [1024]
//   d_in[1] weight_matrix  float32 [16384*16384] row-major
//   d_in[2] biases         float32 [16384]
//   d_in[3] act_ids        int32   [16384]   0=identity 1=relu 2=softsign
//   d_in[4] input_indices  int32   [1024]
//   d_in[5] output_indices int32   [256]
// Output: float32 [256]
//
// out[o] = act( sum_i in_vals[i] * W[in_idx[i], out_idx[o]] + bias[out_idx[o]] )
//
// Single launch, one CTA (256 thr) per output. Fast path (n_in multiple of
// 1024-wide vector tiles): each thread does ONE int4 + ONE float4 metadata
// load, then 4 independent scattered W loads with 32-bit address math
// (row*16384 + j < 2^28, fits int). Short 8-warp reduction, inline finalize.

#define BLOCK 256

__global__ void __launch_bounds__(BLOCK, 4)
custom_network_kernel(const float* __restrict__ in_vals,
                      const float* __restrict__ W,
                      const float* __restrict__ bias,
                      const int*   __restrict__ act_ids,
                      const int*   __restrict__ in_idx,
                      const int*   __restrict__ out_idx,
                      float*       __restrict__ out,
                      int n_in, int N)
{
    const int t = threadIdx.x;
    // Issue the uniform out_idx load and the per-thread metadata loads
    // back-to-back so their latencies overlap.
    const int j = __ldg(&out_idx[blockIdx.x]);

    float p = 0.0f;

    if ((n_in & (4 * BLOCK - 1)) == 0) {
        // fast path: vectorized metadata, 4 W-gathers per tile
        const int4*   idx4 = (const int4*)in_idx;
        const float4* val4 = (const float4*)in_vals;
        const int tiles = n_in >> 10;          // n_in / (4*BLOCK)
        for (int ti = 0; ti < tiles; ti++) {
            const int base = ti * BLOCK + t;
            const int4   r4 = __ldg(&idx4[base]);
            const float4 v4 = __ldg(&val4[base]);
            // 4 independent scattered loads, 32-bit addressing
            const float w0 = __ldg(&W[r4.x * N + j]);
            const float w1 = __ldg(&W[r4.y * N + j]);
            const float w2 = __ldg(&W[r4.z * N + j]);
            const float w3 = __ldg(&W[r4.w * N + j]);
            p += v4.x * w0 + v4.y * w1 + v4.z * w2 + v4.w * w3;
        }
    } else {
        for (int i = t; i < n_in; i += BLOCK) {
            const int r = __ldg(&in_idx[i]);
            p += __ldg(&in_vals[i]) * __ldg(&W[r * N + j]);
        }
    }

    // warp reduce (8 warps) then cross-warp combine
    #pragma unroll
    for (int off = 16; off > 0; off >>= 1)
        p += __shfl_xor_sync(0xFFFFFFFFu, p, off);

    __shared__ float sm[BLOCK / 32];
    const int lane = t & 31;
    const int wid  = t >> 5;
    if (lane == 0) sm[wid] = p;
    __syncthreads();

    if (wid == 0) {
        float v = (lane < BLOCK / 32) ? sm[lane] : 0.0f;
        #pragma unroll
        for (int off = 4; off > 0; off >>= 1)
            v += __shfl_xor_sync(0xFFFFFFFFu, v, off);

        if (lane == 0) {
            const float total = v + __ldg(&bias[j]);
            const int   a     = __ldg(&act_ids[j]);
            const float relu  = fmaxf(total, 0.0f);
            const float ssign = total / (1.0f + fabsf(total));
            out[blockIdx.x] = (a == 1) ? relu : ((a == 2) ? ssign : total);
        }
    }
}

extern "C" void kernel_launch(void* const* d_in, const int* in_sizes, int n_in_args,
                              void* d_out, int out_size)
{
    const float* in_vals = (const float*)d_in[0];
    const float* W       = (const float*)d_in[1];
    const float* bias    = (const float*)d_in[2];
    const int*   act_ids = (const int*)  d_in[3];
    const int*   in_idx  = (const int*)  d_in[4];
    const int*   out_idx = (const int*)  d_in[5];
    float*       out     = (float*)      d_out;

    const int n_in = in_sizes[0];   // 1024
    const int N    = in_sizes[2];   // 16384 (bias length)

    custom_network_kernel<<<out_size, BLOCK>>>(
        in_vals, W, bias, act_ids, in_idx, out_idx, out, n_in, N);
}